// round 1
// baseline (speedup 1.0000x reference)
#include <cuda_runtime.h>
#include <stdint.h>

#define LL 401
#define BB 256
#define PLANE (LL * LL)          // 160801
#define BCH 64                   // batches per chunk
#define NCHUNK (BB / BCH)        // 4

// ---------------- device-global scratch (no allocations allowed) -------------
__device__ double g_bin[LL];     // per-distance-bin sum of cm (over all b,i,j)
__device__ double g_W;           // sum cm * same * maskf
__device__ double g_NC;          // sum relu(cm) * non_conv
__device__ double g_sameCnt;     // sum (same*maskf)
__device__ double g_ncCnt;       // sum non_conv
__device__ unsigned char g_P[BB * LL];   // [b][pos]  bit0=comp bit1=any bit2=f bit3=r
__device__ unsigned char g_PT[LL * BB];  // [pos][b]  transposed copy

// ---------------- zero-init (graph is replayed; must re-zero every launch) ---
__global__ void k_zero() {
    int t = blockIdx.x * blockDim.x + threadIdx.x;
    if (t < LL) g_bin[t] = 0.0;
    if (t == LL) { g_W = 0.0; g_NC = 0.0; g_sameCnt = 0.0; g_ncCnt = 0.0; }
}

// ---------------- pack boolean fields into bytes ----------------------------
__global__ void k_prep(const float* __restrict__ logits, const int* __restrict__ ctcf) {
    int t = blockIdx.x * blockDim.x + threadIdx.x;   // over B*L
    if (t >= BB * LL) return;
    int b = t / LL, pos = t - b * LL;
    float l0 = logits[2 * t], l1 = logits[2 * t + 1];
    int o = ctcf[t];
    unsigned c   = (l1 > l0) ? 1u : 0u;   // argmax over 2 classes, ties -> 0
    unsigned any = (o != 0)  ? 2u : 0u;
    unsigned f   = (o == 1)  ? 4u : 0u;
    unsigned r   = (o == -1) ? 8u : 0u;
    unsigned char byte = (unsigned char)(c | any | f | r);
    g_P[t] = byte;
    g_PT[pos * BB + b] = byte;
}

// ---------------- exact per-batch counts (cm-independent) -------------------
__global__ void k_stats(const float* __restrict__ logits, const int* __restrict__ ctcf) {
    __shared__ unsigned char sc[LL];
    __shared__ int sh[512];
    int b = blockIdx.x, t = threadIdx.x;
    int n1 = 0, F = 0, R = 0, A = 0;
    if (t < LL) {
        int idx = b * LL + t;
        float l0 = logits[2 * idx], l1 = logits[2 * idx + 1];
        unsigned c = (l1 > l0) ? 1u : 0u;
        sc[t] = (unsigned char)c;
        n1 = (int)c;
        int o = ctcf[idx];
        F = (o == 1); R = (o == -1); A = (o != 0);
    }
    __syncthreads();
    int adj = 0;
    if (t < LL - 1) adj = (sc[t] == sc[t + 1]);

    auto redi = [&](int v) -> int {
        sh[t] = v; __syncthreads();
        for (int o = 256; o > 0; o >>= 1) { if (t < o) sh[t] += sh[t + o]; __syncthreads(); }
        int rr = sh[0]; __syncthreads(); return rr;
    };
    int N1 = redi(n1), Fs = redi(F), Rs = redi(R), As = redi(A), Adj = redi(adj);
    if (t == 0) {
        double n1d = (double)N1, n0d = (double)(LL - N1);
        // same pairs with |i-j|>=2 : n0^2+n1^2 minus diag (L, all same) minus d=1 (2*adj)
        atomicAdd(&g_sameCnt, n0d * n0d + n1d * n1d - (double)LL - 2.0 * (double)Adj);
        // non_conv count: A^2 - F*R
        atomicAdd(&g_ncCnt, (double)As * (double)As - (double)Fs * (double)Rs);
    }
}

// ---------------- main pass: thread owns fixed (i,j), loops over b chunk ----
__global__ void __launch_bounds__(256) k_main(const float* __restrict__ cm) {
    int flat = blockIdx.x * 256 + threadIdx.x;
    bool ok = flat < PLANE;
    int fl = ok ? flat : 0;
    int i = fl / LL;
    int j = fl - i * LL;
    int bin = (i > j) ? (i - j) : (j - i);
    unsigned nm = (bin >= 2) ? 0u : 1u;   // OR-mask: forces "same" test false when masked off

    const float* p = cm + (size_t)blockIdx.y * ((size_t)BCH * PLANE) + fl;
    const unsigned char* pj  = g_P  + blockIdx.y * (BCH * LL) + j;
    const unsigned char* pti = g_PT + (size_t)i * BB + blockIdx.y * BCH;

    float accS = 0.f, accW = 0.f, accNC = 0.f;

#pragma unroll 4
    for (int b4 = 0; b4 < BCH; b4 += 4) {
        unsigned ci4 = *reinterpret_cast<const unsigned*>(pti + b4);  // 4 b's of P_i (uniform)
        float v0 = p[0];
        float v1 = p[PLANE];
        float v2 = p[2 * PLANE];
        float v3 = p[3 * PLANE];
        unsigned cj0 = pj[0];
        unsigned cj1 = pj[LL];
        unsigned cj2 = pj[2 * LL];
        unsigned cj3 = pj[3 * LL];
        p  += 4 * (size_t)PLANE;
        pj += 4 * LL;

#define PROC(v, ci, cj) {                                              \
        accS += (v);                                                   \
        unsigned _x = ((ci) ^ (cj)) | nm;                              \
        if ((_x & 1u) == 0u) accW += (v);                              \
        float _rv = fmaxf((v), 0.0f);                                  \
        unsigned _a = (ci) & (cj);                                     \
        bool _conv = (((ci) & 4u) != 0u) & (((cj) & 8u) != 0u);        \
        if (((_a & 2u) != 0u) & (!_conv)) accNC += _rv;                \
    }
        PROC(v0, (ci4      ), cj0);
        PROC(v1, (ci4 >>  8), cj1);
        PROC(v2, (ci4 >> 16), cj2);
        PROC(v3, (ci4 >> 24), cj3);
#undef PROC
    }

    if (ok) atomicAdd(&g_bin[bin], (double)accS);
    if (!ok) { accW = 0.f; accNC = 0.f; }

    // warp reduce the two scalars, one double atomic per warp each
#pragma unroll
    for (int o = 16; o > 0; o >>= 1) {
        accW  += __shfl_down_sync(0xffffffffu, accW,  o);
        accNC += __shfl_down_sync(0xffffffffu, accNC, o);
    }
    if ((threadIdx.x & 31) == 0) {
        atomicAdd(&g_W,  (double)accW);
        atomicAdd(&g_NC, (double)accNC);
    }
}

// ---------------- finalize: regression + loss assembly ----------------------
__global__ void k_final(float* __restrict__ out) {
    __shared__ double sh[512];
    int t = threadIdx.x;

    double bs   = (t < LL) ? g_bin[t] : 0.0;
    double cnt  = (t == 0) ? (double)LL : 2.0 * (double)(LL - t);
    double mean = bs / (cnt * (double)BB);
    bool valid  = (t < LL) && (t >= 2) && isfinite(mean) && (mean > 0.0);
    double w  = valid ? 1.0 : 0.0;
    double ld = log(fmax((double)t, 1.0));
    double lp = log((valid ? mean : 1.0) + 1e-6);

    auto red = [&](double v) -> double {
        sh[t] = v; __syncthreads();
        for (int o = 256; o > 0; o >>= 1) { if (t < o) sh[t] += sh[t + o]; __syncthreads(); }
        double rr = sh[0]; __syncthreads(); return rr;
    };

    double n  = red(w);
    double sx = red(w * ld);
    double sy = red(w * lp);
    double nsafe = fmax(n, 1.0);
    double xm = sx / nsafe, ym = sy / nsafe;
    double num = red(w * (ld - xm) * (lp - ym));
    double den = red(w * (ld - xm) * (ld - xm)) + 1e-8;
    double totMasked = red((t >= 2 && t < LL) ? bs : 0.0);  // sum cm over |i-j|>=2

    if (t == 0) {
        double slope = num / den;
        double dist  = (n >= 5.0) ? (slope + 0.85) * (slope + 0.85) : 0.0;

        double ncC  = g_ncCnt;
        double ctcf = (ncC < 1.0) ? 0.0 : g_NC / (ncC + 1e-6);

        double sameC = g_sameCnt;
        double diffC = (double)BB * ((double)LL * LL - 3.0 * LL + 2.0) - sameC;
        double within  = g_W / fmax(sameC, 1.0);
        double between = (totMasked - g_W) / fmax(diffC, 1.0);
        double ratio   = within / (fabs(between) + 1e-6);
        double comp    = fmax(0.0, 1.5 - ratio);

        out[0] = (float)dist;
        out[1] = (float)ctcf;
        out[2] = (float)comp;
        out[3] = (float)(dist + 0.5 * ctcf + 0.5 * comp);
    }
}

// ---------------- launch ----------------------------------------------------
extern "C" void kernel_launch(void* const* d_in, const int* in_sizes, int n_in,
                              void* d_out, int out_size) {
    const float* cm     = (const float*)d_in[0];
    const float* logits = (const float*)d_in[1];
    const int*   ctcf   = (const int*)d_in[2];
    float* out = (float*)d_out;

    k_zero<<<2, 256>>>();
    k_prep<<<(BB * LL + 255) / 256, 256>>>(logits, ctcf);
    k_stats<<<BB, 512>>>(logits, ctcf);
    k_main<<<dim3((PLANE + 255) / 256, NCHUNK), 256>>>(cm);
    k_final<<<1, 512>>>(out);
}

// round 2
// speedup vs baseline: 1.1687x; 1.1687x over previous
#include <cuda_runtime.h>
#include <stdint.h>

#define LL 401
#define BB 256
#define PLANE (LL * LL)          // 160801
#define BCH 64                   // batches per chunk
#define NCHUNK 4                 // BB / BCH

// ---------------- device-global scratch (no allocations allowed) -------------
__device__ double g_bin[LL];             // per-distance-bin sum of cm
__device__ double g_W;                   // sum cm * same * maskf
__device__ double g_NC;                  // sum relu(cm) * non_conv
__device__ double g_bSame[BB];           // per-batch same*maskf count
__device__ double g_bNc[BB];             // per-batch non_conv count
__device__ unsigned char g_P[BB * LL];   // [b][pos]  bit0=comp bit1=any bit2=f bit3=r
__device__ unsigned char g_PT[LL * BB];  // [pos][b]  transposed copy

// ---------------- prep: pack bytes + per-batch counts + zero globals ---------
__global__ void k_prep(const float2* __restrict__ logits, const int* __restrict__ ctcf) {
    int b = blockIdx.x, t = threadIdx.x;
    if (b == 0) {                         // zero accumulators (graph is replayed)
        if (t < LL) g_bin[t] = 0.0;
        if (t == LL) { g_W = 0.0; g_NC = 0.0; }
    }
    __shared__ unsigned char sc[LL];
    __shared__ unsigned long long shw[16];
    unsigned long long pack = 0ull;
    if (t < LL) {
        int idx = b * LL + t;
        float2 l = logits[idx];
        int o = ctcf[idx];
        unsigned c = (l.y > l.x) ? 1u : 0u;      // argmax of 2 logits (tie -> 0)
        unsigned A = (o != 0) ? 1u : 0u;
        unsigned F = (o == 1) ? 1u : 0u;
        unsigned R = (o == -1) ? 1u : 0u;
        unsigned char byte = (unsigned char)(c | (A << 1) | (F << 2) | (R << 3));
        g_P[idx] = byte;
        g_PT[t * BB + b] = byte;
        sc[t] = (unsigned char)c;
        pack = (unsigned long long)c
             | ((unsigned long long)F << 24)
             | ((unsigned long long)R << 36)
             | ((unsigned long long)A << 48);
    }
    __syncthreads();
    if (t < LL - 1) pack |= ((unsigned long long)(sc[t] == sc[t + 1] ? 1u : 0u)) << 12;

#pragma unroll
    for (int o = 16; o > 0; o >>= 1) pack += __shfl_down_sync(0xffffffffu, pack, o);
    if ((t & 31) == 0) shw[t >> 5] = pack;
    __syncthreads();
    if (t == 0) {
        unsigned long long s = 0;
        for (int w = 0; w < 16; w++) s += shw[w];
        double n1  = (double)(s & 0xFFFull);
        double adj = (double)((s >> 12) & 0xFFFull);
        double F   = (double)((s >> 24) & 0xFFFull);
        double R   = (double)((s >> 36) & 0xFFFull);
        double A   = (double)((s >> 48) & 0xFFFull);
        double n0  = (double)LL - n1;
        // same pairs with |i-j|>=2: n0^2+n1^2 - diag(L) - dist1(2*adj)
        g_bSame[b] = n0 * n0 + n1 * n1 - (double)LL - 2.0 * adj;
        g_bNc[b]   = A * A - F * R;       // non_conv count = A^2 - F*R
    }
}

// ---------------- main pass: thread owns fixed (i,j), loops over b chunk ----
__global__ void __launch_bounds__(256, 5) k_main(const float* __restrict__ cm) {
    int flat = blockIdx.x * 256 + threadIdx.x;
    bool ok = flat < PLANE;
    int fl = ok ? flat : 0;
    int i = fl / LL;
    int j = fl - i * LL;
    int bin = (i > j) ? (i - j) : (j - i);
    unsigned nm = (bin >= 2) ? 0u : 1u;   // OR-mask: kills "same" test when masked

    int b0 = blockIdx.y * BCH;
    const float* p = cm + (size_t)b0 * PLANE + fl;
    const unsigned char* pj  = g_P  + b0 * LL + j;
    const unsigned char* pti = g_PT + i * BB + b0;     // 8B-aligned (i*256 + k*64)

    float accS = 0.f, accW = 0.f, accNC = 0.f;

    for (int bb = 0; bb < BCH; bb += 8) {
        float v[8];
        unsigned cj[8];
#pragma unroll
        for (int k = 0; k < 8; k++) v[k] = __ldg(p + (size_t)(bb + k) * PLANE);
#pragma unroll
        for (int k = 0; k < 8; k++) cj[k] = pj[(bb + k) * LL];
        uint2 ci8 = *reinterpret_cast<const uint2*>(pti + bb);

#pragma unroll
        for (int k = 0; k < 8; k++) {
            unsigned ci = (k < 4) ? (ci8.x >> (8 * k)) : (ci8.y >> (8 * (k - 4)));
            float vv = v[k];
            accS += vv;
            if ((((ci ^ cj[k]) | nm) & 1u) == 0u) accW += vv;
            unsigned x = ci & cj[k];              // bit1 = any&any
            unsigned y = (ci << 1) & cj[k];       // bit3 = f_i & r_j (convergent)
            if ((x & ~(y >> 2) & 2u) != 0u) accNC += fmaxf(vv, 0.0f);
        }
    }

    if (ok) atomicAdd(&g_bin[bin], (double)accS);
    if (!ok) { accW = 0.f; accNC = 0.f; }

    // block-reduce the two scalars -> 2 double atomics per block
#pragma unroll
    for (int o = 16; o > 0; o >>= 1) {
        accW  += __shfl_down_sync(0xffffffffu, accW,  o);
        accNC += __shfl_down_sync(0xffffffffu, accNC, o);
    }
    __shared__ double sW[8], sN[8];
    if ((threadIdx.x & 31) == 0) { sW[threadIdx.x >> 5] = accW; sN[threadIdx.x >> 5] = accNC; }
    __syncthreads();
    if (threadIdx.x == 0) {
        double w = 0.0, nn = 0.0;
#pragma unroll
        for (int q = 0; q < 8; q++) { w += sW[q]; nn += sN[q]; }
        atomicAdd(&g_W, w);
        atomicAdd(&g_NC, nn);
    }
}

// ---------------- finalize: regression + loss assembly ----------------------
__device__ __forceinline__ double blockRed(double v, double* sh) {
    int t = threadIdx.x;
#pragma unroll
    for (int o = 16; o > 0; o >>= 1) v += __shfl_down_sync(0xffffffffu, v, o);
    if ((t & 31) == 0) sh[t >> 5] = v;
    __syncthreads();
    if (t < 32) {
        double w = (t < 16) ? sh[t] : 0.0;
#pragma unroll
        for (int o = 8; o > 0; o >>= 1) w += __shfl_down_sync(0xffffffffu, w, o);
        if (t == 0) sh[0] = w;
    }
    __syncthreads();
    double r = sh[0];
    __syncthreads();
    return r;
}

__global__ void k_final(float* __restrict__ out) {
    __shared__ double sh[16];
    int t = threadIdx.x;

    double bs   = (t < LL) ? g_bin[t] : 0.0;
    double cnt  = (t == 0) ? (double)LL : 2.0 * (double)(LL - t);
    double mean = bs / (cnt * (double)BB);
    bool valid  = (t < LL) && (t >= 2) && isfinite(mean) && (mean > 0.0);
    double w  = valid ? 1.0 : 0.0;
    double ld = log(fmax((double)t, 1.0));
    double lp = log((valid ? mean : 1.0) + 1e-6);

    double n     = blockRed(w, sh);
    double sx    = blockRed(w * ld, sh);
    double sy    = blockRed(w * lp, sh);
    double tm    = blockRed((t >= 2 && t < LL) ? bs : 0.0, sh);   // total masked cm sum
    double sameC = blockRed((t < BB) ? g_bSame[t] : 0.0, sh);
    double ncC   = blockRed((t < BB) ? g_bNc[t]   : 0.0, sh);

    double nsafe = fmax(n, 1.0);
    double xm = sx / nsafe, ym = sy / nsafe;
    double num = blockRed(w * (ld - xm) * (lp - ym), sh);
    double den = blockRed(w * (ld - xm) * (ld - xm), sh) + 1e-8;

    if (t == 0) {
        double slope = num / den;
        double dist  = (n >= 5.0) ? (slope + 0.85) * (slope + 0.85) : 0.0;

        double ctcf = (ncC < 1.0) ? 0.0 : g_NC / (ncC + 1e-6);

        double diffC   = (double)BB * ((double)LL * LL - 3.0 * LL + 2.0) - sameC;
        double within  = g_W / fmax(sameC, 1.0);
        double between = (tm - g_W) / fmax(diffC, 1.0);
        double ratio   = within / (fabs(between) + 1e-6);
        double comp    = fmax(0.0, 1.5 - ratio);

        out[0] = (float)dist;
        out[1] = (float)ctcf;
        out[2] = (float)comp;
        out[3] = (float)(dist + 0.5 * ctcf + 0.5 * comp);
    }
}

// ---------------- launch ----------------------------------------------------
extern "C" void kernel_launch(void* const* d_in, const int* in_sizes, int n_in,
                              void* d_out, int out_size) {
    const float* cm      = (const float*)d_in[0];
    const float2* logits = (const float2*)d_in[1];
    const int*   ctcf    = (const int*)d_in[2];
    float* out = (float*)d_out;

    k_prep<<<BB, 512>>>(logits, ctcf);
    k_main<<<dim3((PLANE + 255) / 256, NCHUNK), 256>>>(cm);
    k_final<<<1, 512>>>(out);
}

// round 3
// speedup vs baseline: 1.2688x; 1.0856x over previous
#include <cuda_runtime.h>
#include <stdint.h>

#define LL 401
#define BB 256
#define PLANE (LL * LL)          // 160801
#define BCH 64                   // batches per chunk
#define NCHUNK 4                 // BB / BCH
#define GX ((PLANE + 255) / 256) // 629
#define NBLK (GX * NCHUNK)       // 2516

// ---------------- device-global scratch (no allocations allowed) -------------
__device__ double g_bin[LL];             // per-distance-bin sum of cm
__device__ double g_W;                   // sum cm * same * maskf
__device__ double g_NC;                  // sum relu(cm) * non_conv
__device__ double g_bSame[BB];           // per-batch same*maskf count
__device__ double g_bNc[BB];             // per-batch non_conv count
__device__ unsigned char g_PT[LL * BB];  // [pos][b]  bit0=comp bit1=any bit2=f bit3=r
__device__ unsigned int g_done;          // last-block-done counter (self-resetting)

// ---------------- prep: pack bytes + per-batch counts + zero globals ---------
__global__ void k_prep(const float2* __restrict__ logits, const int* __restrict__ ctcf) {
    int b = blockIdx.x, t = threadIdx.x;
    if (b == 0) {                         // zero accumulators (graph is replayed)
        if (t < LL) g_bin[t] = 0.0;
        if (t == LL) { g_W = 0.0; g_NC = 0.0; }
    }
    __shared__ unsigned char sc[LL];
    __shared__ unsigned long long shw[16];
    unsigned long long pack = 0ull;
    if (t < LL) {
        int idx = b * LL + t;
        float2 l = logits[idx];
        int o = ctcf[idx];
        unsigned c = (l.y > l.x) ? 1u : 0u;      // argmax of 2 logits (tie -> 0)
        unsigned A = (o != 0) ? 1u : 0u;
        unsigned F = (o == 1) ? 1u : 0u;
        unsigned R = (o == -1) ? 1u : 0u;
        g_PT[t * BB + b] = (unsigned char)(c | (A << 1) | (F << 2) | (R << 3));
        sc[t] = (unsigned char)c;
        pack = (unsigned long long)c
             | ((unsigned long long)F << 24)
             | ((unsigned long long)R << 36)
             | ((unsigned long long)A << 48);
    }
    __syncthreads();
    if (t < LL - 1) pack |= ((unsigned long long)(sc[t] == sc[t + 1] ? 1u : 0u)) << 12;

#pragma unroll
    for (int o = 16; o > 0; o >>= 1) pack += __shfl_down_sync(0xffffffffu, pack, o);
    if ((t & 31) == 0) shw[t >> 5] = pack;
    __syncthreads();
    if (t == 0) {
        unsigned long long s = 0;
        for (int w = 0; w < 16; w++) s += shw[w];
        double n1  = (double)(s & 0xFFFull);
        double adj = (double)((s >> 12) & 0xFFFull);
        double F   = (double)((s >> 24) & 0xFFFull);
        double R   = (double)((s >> 36) & 0xFFFull);
        double A   = (double)((s >> 48) & 0xFFFull);
        double n0  = (double)LL - n1;
        g_bSame[b] = n0 * n0 + n1 * n1 - (double)LL - 2.0 * adj;  // same & |i-j|>=2
        g_bNc[b]   = A * A - F * R;                               // non_conv count
    }
}

// ---------------- block reduction over 256 threads --------------------------
__device__ __forceinline__ double blockRed256(double v, double* sh) {
    int t = threadIdx.x;
#pragma unroll
    for (int o = 16; o > 0; o >>= 1) v += __shfl_down_sync(0xffffffffu, v, o);
    if ((t & 31) == 0) sh[t >> 5] = v;
    __syncthreads();
    double r;
    if (t < 32) {
        double w = (t < 8) ? sh[t] : 0.0;
#pragma unroll
        for (int o = 4; o > 0; o >>= 1) w += __shfl_down_sync(0xffffffffu, w, o);
        if (t == 0) sh[0] = w;
    }
    __syncthreads();
    r = sh[0];
    __syncthreads();
    return r;
}

// ---------------- main pass + fused finalize --------------------------------
__global__ void __launch_bounds__(256, 4) k_main(const float* __restrict__ cm,
                                                 float* __restrict__ out) {
    int flat = blockIdx.x * 256 + threadIdx.x;
    bool ok = flat < PLANE;
    int fl = ok ? flat : 0;
    int i = fl / LL;
    int j = fl - i * LL;
    int bin = (i > j) ? (i - j) : (j - i);
    unsigned nm = (bin >= 2) ? 0u : 1u;   // OR-mask: kills "same" test when masked

    int b0 = blockIdx.y * BCH;
    const float* p = cm + (size_t)b0 * PLANE + fl;
    const unsigned char* ptI = g_PT + i * BB + b0;   // 8B-aligned
    const unsigned char* ptJ = g_PT + j * BB + b0;

    float accS = 0.f, accW = 0.f, accNC = 0.f;

    // prologue: first batch of 8
    float v[8]; uint2 ciw, cjw;
#pragma unroll
    for (int k = 0; k < 8; k++) v[k] = __ldg(p + (size_t)k * PLANE);
    ciw = *reinterpret_cast<const uint2*>(ptI);
    cjw = *reinterpret_cast<const uint2*>(ptJ);

#pragma unroll
    for (int bb = 0; bb < BCH; bb += 8) {
        float vn[8]; uint2 cin, cjn;
        if (bb + 8 < BCH) {               // prefetch next batch
            const float* pn = p + (size_t)8 * PLANE;
#pragma unroll
            for (int k = 0; k < 8; k++) vn[k] = __ldg(pn + (size_t)k * PLANE);
            cin = *reinterpret_cast<const uint2*>(ptI + 8);
            cjn = *reinterpret_cast<const uint2*>(ptJ + 8);
        }

#pragma unroll
        for (int k = 0; k < 8; k++) {
            unsigned ci = (k < 4) ? (ciw.x >> (8 * k)) : (ciw.y >> (8 * (k - 4)));
            unsigned cj = (k < 4) ? (cjw.x >> (8 * k)) : (cjw.y >> (8 * (k - 4)));
            float vv = v[k];
            accS += vv;
            if ((((ci ^ cj) | nm) & 1u) == 0u) accW += vv;
            unsigned x = ci & cj;              // bit1 = any_i & any_j
            unsigned y = (ci << 1) & cj;       // bit3 = f_i & r_j (convergent)
            if ((x & ~(y >> 2) & 2u) != 0u) accNC += fmaxf(vv, 0.0f);
        }

#pragma unroll
        for (int k = 0; k < 8; k++) v[k] = vn[k];
        ciw = cin; cjw = cjn;
        p += (size_t)8 * PLANE; ptI += 8; ptJ += 8;
    }

    if (ok) atomicAdd(&g_bin[bin], (double)accS);
    if (!ok) { accW = 0.f; accNC = 0.f; }

    // block-reduce the two scalars -> 2 double atomics per block
#pragma unroll
    for (int o = 16; o > 0; o >>= 1) {
        accW  += __shfl_down_sync(0xffffffffu, accW,  o);
        accNC += __shfl_down_sync(0xffffffffu, accNC, o);
    }
    __shared__ double sW[8], sN[8];
    if ((threadIdx.x & 31) == 0) { sW[threadIdx.x >> 5] = accW; sN[threadIdx.x >> 5] = accNC; }
    __syncthreads();
    if (threadIdx.x == 0) {
        double w = 0.0, nn = 0.0;
#pragma unroll
        for (int q = 0; q < 8; q++) { w += sW[q]; nn += sN[q]; }
        atomicAdd(&g_W, w);
        atomicAdd(&g_NC, nn);
    }

    // ---------- last-block-done: fused finalize ----------
    __shared__ bool isLast;
    __threadfence();
    if (threadIdx.x == 0) {
        unsigned v0 = atomicAdd(&g_done, 1u);
        isLast = (v0 == (unsigned)(NBLK - 1));
    }
    __syncthreads();
    if (!isLast) return;
    if (threadIdx.x == 0) g_done = 0;    // reset for next graph replay
    __threadfence();

    {
        __shared__ double sh[8];
        int t = threadIdx.x;
        int t1 = t + 256;

        double bs0 = (t  < LL) ? g_bin[t]  : 0.0;
        double bs1 = (t1 < LL) ? g_bin[t1] : 0.0;
        double cnt0 = (t == 0) ? (double)LL : 2.0 * (double)(LL - t);
        double cnt1 = 2.0 * (double)(LL - t1);
        double mean0 = bs0 / (cnt0 * (double)BB);
        double mean1 = (t1 < LL) ? bs1 / (cnt1 * (double)BB) : 0.0;
        bool va0 = (t  < LL) && (t  >= 2) && isfinite(mean0) && (mean0 > 0.0);
        bool va1 = (t1 < LL)              && isfinite(mean1) && (mean1 > 0.0);
        double w0 = va0 ? 1.0 : 0.0, w1 = va1 ? 1.0 : 0.0;
        double ld0 = log(fmax((double)t, 1.0));
        double ld1 = log((double)t1);
        double lp0 = log((va0 ? mean0 : 1.0) + 1e-6);
        double lp1 = log((va1 ? mean1 : 1.0) + 1e-6);

        double n     = blockRed256(w0 + w1, sh);
        double sx    = blockRed256(w0 * ld0 + w1 * ld1, sh);
        double sy    = blockRed256(w0 * lp0 + w1 * lp1, sh);
        double tm    = blockRed256(((t >= 2 && t < LL) ? bs0 : 0.0) +
                                   ((t1 < LL) ? bs1 : 0.0), sh);
        double sameC = blockRed256(g_bSame[t], sh);     // exactly 256 batches
        double ncC   = blockRed256(g_bNc[t], sh);

        double nsafe = fmax(n, 1.0);
        double xm = sx / nsafe, ym = sy / nsafe;
        double num = blockRed256(w0 * (ld0 - xm) * (lp0 - ym) +
                                 w1 * (ld1 - xm) * (lp1 - ym), sh);
        double den = blockRed256(w0 * (ld0 - xm) * (ld0 - xm) +
                                 w1 * (ld1 - xm) * (ld1 - xm), sh) + 1e-8;

        if (t == 0) {
            double slope = num / den;
            double dist  = (n >= 5.0) ? (slope + 0.85) * (slope + 0.85) : 0.0;

            double ctcf = (ncC < 1.0) ? 0.0 : g_NC / (ncC + 1e-6);

            double diffC   = (double)BB * ((double)LL * LL - 3.0 * LL + 2.0) - sameC;
            double within  = g_W / fmax(sameC, 1.0);
            double between = (tm - g_W) / fmax(diffC, 1.0);
            double ratio   = within / (fabs(between) + 1e-6);
            double comp    = fmax(0.0, 1.5 - ratio);

            out[0] = (float)dist;
            out[1] = (float)ctcf;
            out[2] = (float)comp;
            out[3] = (float)(dist + 0.5 * ctcf + 0.5 * comp);
        }
    }
}

// ---------------- launch ----------------------------------------------------
extern "C" void kernel_launch(void* const* d_in, const int* in_sizes, int n_in,
                              void* d_out, int out_size) {
    const float* cm      = (const float*)d_in[0];
    const float2* logits = (const float2*)d_in[1];
    const int*   ctcf    = (const int*)d_in[2];
    float* out = (float*)d_out;

    k_prep<<<BB, 512>>>(logits, ctcf);
    k_main<<<dim3(GX, NCHUNK), 256>>>(cm, out);
}

// round 4
// speedup vs baseline: 1.2861x; 1.0136x over previous
#include <cuda_runtime.h>
#include <stdint.h>

#define LL 401
#define BB 256
#define PLANE (LL * LL)          // 160801
#define BCH 64                   // batches per chunk
#define NCHUNK 4                 // BB / BCH
#define GX ((PLANE + 255) / 256) // 629
#define NBLK (GX * NCHUNK)       // 2516

// ---------------- device-global scratch (no allocations allowed) -------------
__device__ double g_bin[LL];             // per-distance-bin sum of cm
__device__ double g_W;                   // sum cm * same * maskf
__device__ double g_NC;                  // sum relu(cm) * non_conv
__device__ double g_bSame[BB];           // per-batch same*maskf count
__device__ double g_bNc[BB];             // per-batch non_conv count
__device__ unsigned char g_P [BB * LL];  // [b][pos]  bit0=comp bit1=any bit2=f bit3=r
__device__ unsigned char g_PT[LL * BB];  // [pos][b]  transposed copy (for ci broadcast)
__device__ unsigned int g_done;          // last-block-done counter (self-resetting)

// ---------------- prep: pack bytes + per-batch counts + zero globals ---------
__global__ void k_prep(const float2* __restrict__ logits, const int* __restrict__ ctcf) {
    int b = blockIdx.x, t = threadIdx.x;
    if (b == 0) {                         // zero accumulators (graph is replayed)
        if (t < LL) g_bin[t] = 0.0;
        if (t == LL) { g_W = 0.0; g_NC = 0.0; }
    }
    __shared__ unsigned char sc[LL];
    __shared__ unsigned long long shw[16];
    unsigned long long pack = 0ull;
    if (t < LL) {
        int idx = b * LL + t;
        float2 l = logits[idx];
        int o = ctcf[idx];
        unsigned c = (l.y > l.x) ? 1u : 0u;      // argmax of 2 logits (tie -> 0)
        unsigned A = (o != 0) ? 1u : 0u;
        unsigned F = (o == 1) ? 1u : 0u;
        unsigned R = (o == -1) ? 1u : 0u;
        unsigned char byte = (unsigned char)(c | (A << 1) | (F << 2) | (R << 3));
        g_P[idx] = byte;
        g_PT[t * BB + b] = byte;
        sc[t] = (unsigned char)c;
        pack = (unsigned long long)c
             | ((unsigned long long)F << 24)
             | ((unsigned long long)R << 36)
             | ((unsigned long long)A << 48);
    }
    __syncthreads();
    if (t < LL - 1) pack |= ((unsigned long long)(sc[t] == sc[t + 1] ? 1u : 0u)) << 12;

#pragma unroll
    for (int o = 16; o > 0; o >>= 1) pack += __shfl_down_sync(0xffffffffu, pack, o);
    if ((t & 31) == 0) shw[t >> 5] = pack;
    __syncthreads();
    if (t == 0) {
        unsigned long long s = 0;
        for (int w = 0; w < 16; w++) s += shw[w];
        double n1  = (double)(s & 0xFFFull);
        double adj = (double)((s >> 12) & 0xFFFull);
        double F   = (double)((s >> 24) & 0xFFFull);
        double R   = (double)((s >> 36) & 0xFFFull);
        double A   = (double)((s >> 48) & 0xFFFull);
        double n0  = (double)LL - n1;
        g_bSame[b] = n0 * n0 + n1 * n1 - (double)LL - 2.0 * adj;  // same & |i-j|>=2
        g_bNc[b]   = A * A - F * R;                               // non_conv count
    }
}

// ---------------- block reduction over 256 threads --------------------------
__device__ __forceinline__ double blockRed256(double v, double* sh) {
    int t = threadIdx.x;
#pragma unroll
    for (int o = 16; o > 0; o >>= 1) v += __shfl_down_sync(0xffffffffu, v, o);
    if ((t & 31) == 0) sh[t >> 5] = v;
    __syncthreads();
    double r;
    if (t < 32) {
        double w = (t < 8) ? sh[t] : 0.0;
#pragma unroll
        for (int o = 4; o > 0; o >>= 1) w += __shfl_down_sync(0xffffffffu, w, o);
        if (t == 0) sh[0] = w;
    }
    __syncthreads();
    r = sh[0];
    __syncthreads();
    return r;
}

// ---------------- main pass + fused finalize --------------------------------
__global__ void __launch_bounds__(256, 4) k_main(const float* __restrict__ cm,
                                                 float* __restrict__ out) {
    int flat = blockIdx.x * 256 + threadIdx.x;
    bool ok = flat < PLANE;
    int fl = ok ? flat : 0;
    int i = fl / LL;
    int j = fl - i * LL;
    int bin = (i > j) ? (i - j) : (j - i);
    unsigned nm = (bin >= 2) ? 0u : 1u;   // OR-mask: kills "same" test when masked

    int b0 = blockIdx.y * BCH;
    const float* p = cm + (size_t)b0 * PLANE + fl;
    const unsigned char* pj  = g_P  + b0 * LL + j;   // coalesced: lane-consecutive bytes
    const unsigned char* ptI = g_PT + i * BB + b0;   // broadcast: same addr all lanes

    float accS = 0.f, accW = 0.f, accNC = 0.f;

    // prologue: first batch of 8
    float v[8]; unsigned cj[8]; uint2 ciw;
#pragma unroll
    for (int k = 0; k < 8; k++) v[k] = __ldg(p + (size_t)k * PLANE);
#pragma unroll
    for (int k = 0; k < 8; k++) cj[k] = pj[k * LL];
    ciw = *reinterpret_cast<const uint2*>(ptI);

#pragma unroll
    for (int bb = 0; bb < BCH; bb += 8) {
        float vn[8]; unsigned cjn[8]; uint2 cin;
        if (bb + 8 < BCH) {               // prefetch next batch of 8
            const float* pn = p + (size_t)8 * PLANE;
            const unsigned char* pjn = pj + 8 * LL;
#pragma unroll
            for (int k = 0; k < 8; k++) vn[k] = __ldg(pn + (size_t)k * PLANE);
#pragma unroll
            for (int k = 0; k < 8; k++) cjn[k] = pjn[k * LL];
            cin = *reinterpret_cast<const uint2*>(ptI + 8);
        }

#pragma unroll
        for (int k = 0; k < 8; k++) {
            unsigned ci = (k < 4) ? (ciw.x >> (8 * k)) : (ciw.y >> (8 * (k - 4)));
            float vv = v[k];
            accS += vv;
            if ((((ci ^ cj[k]) | nm) & 1u) == 0u) accW += vv;
            unsigned x = ci & cj[k];              // bit1 = any_i & any_j
            unsigned y = (ci << 1) & cj[k];       // bit3 = f_i & r_j (convergent)
            if ((x & ~(y >> 2) & 2u) != 0u) accNC += fmaxf(vv, 0.0f);
        }

#pragma unroll
        for (int k = 0; k < 8; k++) { v[k] = vn[k]; cj[k] = cjn[k]; }
        ciw = cin;
        p += (size_t)8 * PLANE; pj += 8 * LL; ptI += 8;
    }

    if (ok) atomicAdd(&g_bin[bin], (double)accS);
    if (!ok) { accW = 0.f; accNC = 0.f; }

    // block-reduce the two scalars -> 2 double atomics per block
#pragma unroll
    for (int o = 16; o > 0; o >>= 1) {
        accW  += __shfl_down_sync(0xffffffffu, accW,  o);
        accNC += __shfl_down_sync(0xffffffffu, accNC, o);
    }
    __shared__ double sW[8], sN[8];
    if ((threadIdx.x & 31) == 0) { sW[threadIdx.x >> 5] = accW; sN[threadIdx.x >> 5] = accNC; }
    __syncthreads();
    if (threadIdx.x == 0) {
        double w = 0.0, nn = 0.0;
#pragma unroll
        for (int q = 0; q < 8; q++) { w += sW[q]; nn += sN[q]; }
        atomicAdd(&g_W, w);
        atomicAdd(&g_NC, nn);
    }

    // ---------- last-block-done: fused finalize ----------
    __shared__ bool isLast;
    __threadfence();
    if (threadIdx.x == 0) {
        unsigned v0 = atomicAdd(&g_done, 1u);
        isLast = (v0 == (unsigned)(NBLK - 1));
    }
    __syncthreads();
    if (!isLast) return;
    if (threadIdx.x == 0) g_done = 0;    // reset for next graph replay
    __threadfence();

    {
        __shared__ double sh[8];
        int t = threadIdx.x;
        int t1 = t + 256;

        double bs0 = (t  < LL) ? g_bin[t]  : 0.0;
        double bs1 = (t1 < LL) ? g_bin[t1] : 0.0;
        double cnt0 = (t == 0) ? (double)LL : 2.0 * (double)(LL - t);
        double cnt1 = 2.0 * (double)(LL - t1);
        double mean0 = bs0 / (cnt0 * (double)BB);
        double mean1 = (t1 < LL) ? bs1 / (cnt1 * (double)BB) : 0.0;
        bool va0 = (t  < LL) && (t  >= 2) && isfinite(mean0) && (mean0 > 0.0);
        bool va1 = (t1 < LL)              && isfinite(mean1) && (mean1 > 0.0);
        double w0 = va0 ? 1.0 : 0.0, w1 = va1 ? 1.0 : 0.0;
        double ld0 = log(fmax((double)t, 1.0));
        double ld1 = log((double)t1);
        double lp0 = log((va0 ? mean0 : 1.0) + 1e-6);
        double lp1 = log((va1 ? mean1 : 1.0) + 1e-6);

        double n     = blockRed256(w0 + w1, sh);
        double sx    = blockRed256(w0 * ld0 + w1 * ld1, sh);
        double sy    = blockRed256(w0 * lp0 + w1 * lp1, sh);
        double tm    = blockRed256(((t >= 2 && t < LL) ? bs0 : 0.0) +
                                   ((t1 < LL) ? bs1 : 0.0), sh);
        double sameC = blockRed256(g_bSame[t], sh);     // exactly 256 batches
        double ncC   = blockRed256(g_bNc[t], sh);

        double nsafe = fmax(n, 1.0);
        double xm = sx / nsafe, ym = sy / nsafe;
        double num = blockRed256(w0 * (ld0 - xm) * (lp0 - ym) +
                                 w1 * (ld1 - xm) * (lp1 - ym), sh);
        double den = blockRed256(w0 * (ld0 - xm) * (ld0 - xm) +
                                 w1 * (ld1 - xm) * (ld1 - xm), sh) + 1e-8;

        if (t == 0) {
            double slope = num / den;
            double dist  = (n >= 5.0) ? (slope + 0.85) * (slope + 0.85) : 0.0;

            double ctcf = (ncC < 1.0) ? 0.0 : g_NC / (ncC + 1e-6);

            double diffC   = (double)BB * ((double)LL * LL - 3.0 * LL + 2.0) - sameC;
            double within  = g_W / fmax(sameC, 1.0);
            double between = (tm - g_W) / fmax(diffC, 1.0);
            double ratio   = within / (fabs(between) + 1e-6);
            double comp    = fmax(0.0, 1.5 - ratio);

            out[0] = (float)dist;
            out[1] = (float)ctcf;
            out[2] = (float)comp;
            out[3] = (float)(dist + 0.5 * ctcf + 0.5 * comp);
        }
    }
}

// ---------------- launch ----------------------------------------------------
extern "C" void kernel_launch(void* const* d_in, const int* in_sizes, int n_in,
                              void* d_out, int out_size) {
    const float* cm      = (const float*)d_in[0];
    const float2* logits = (const float2*)d_in[1];
    const int*   ctcf    = (const int*)d_in[2];
    float* out = (float*)d_out;

    k_prep<<<BB, 512>>>(logits, ctcf);
    k_main<<<dim3(GX, NCHUNK), 256>>>(cm, out);
}